// round 7
// baseline (speedup 1.0000x reference)
#include <cuda_runtime.h>
#include <cuda_bf16.h>
#include <cstdint>

// Problem constants (fixed by the dataset)
#define K_DIM 256
#define N_DIM 64
#define MAX_NODES 100000
#define MAX_EDGES 1310720
#define SCAN_BLK 1024
#define MAX_SCAN_BLOCKS ((MAX_NODES + SCAN_BLK - 1) / SCAN_BLK + 2)

// Device scratch (no cudaMalloc allowed)
__device__ float g_pre[(size_t)MAX_NODES * N_DIM];          // X @ W
__device__ int g_idx64;                                      // index dtype flag
__device__ int g_row_cnt[MAX_NODES];                         // counts, then cursor
__device__ int g_row_off[MAX_NODES + 1];                     // CSR offsets
__device__ unsigned long long g_edge_cv[MAX_EDGES];          // packed (val,col)
__device__ int g_scan_part[MAX_SCAN_BLOCKS];                 // scan partials

// ===========================================================================
// Kernel 0: detect index dtype. int64 values < 2^31 have zero high words.
// ===========================================================================
__global__ void detect_idx_kernel(const unsigned int* __restrict__ rows_u32, int E)
{
    __shared__ int any_nonzero;
    if (threadIdx.x == 0) any_nonzero = 0;
    __syncthreads();
    int n = E < 4096 ? E : 4096;
    for (int i = threadIdx.x; i < n; i += blockDim.x)
        if (rows_u32[2 * i + 1] != 0u) any_nonzero = 1;   // benign smem race
    __syncthreads();
    if (threadIdx.x == 0) g_idx64 = any_nonzero ? 0 : 1;
}

__device__ __forceinline__ int load_idx(const void* p, int e)
{
    return g_idx64 ? (int)((const long long*)p)[e] : ((const int*)p)[e];
}

// ===========================================================================
// GEMM  pre_sup[M,64] = X[M,256] @ W[256,64] via mma.sync bf16x3,
// software-pipelined: next kstep's A loads issued before current MMAs.
// ===========================================================================
#define WS_STRIDE 68   // u64 per n-row

__device__ __forceinline__ void mma_bf16(float* d, uint32_t a0, uint32_t a1,
                                         uint32_t a2, uint32_t a3,
                                         uint32_t b0, uint32_t b1)
{
    asm volatile(
        "mma.sync.aligned.m16n8k16.row.col.f32.bf16.bf16.f32 "
        "{%0, %1, %2, %3}, {%4, %5, %6, %7}, {%8, %9}, {%0, %1, %2, %3};"
        : "+f"(d[0]), "+f"(d[1]), "+f"(d[2]), "+f"(d[3])
        : "r"(a0), "r"(a1), "r"(a2), "r"(a3), "r"(b0), "r"(b1));
}

// fast 2-way bf16 split of a float pair: hi = packed bf16(x0,x1) (x0 low),
// lo = packed bf16 of residuals. bf16->f32 via shift/mask (exact).
__device__ __forceinline__ void split_pair(float x0, float x1,
                                           uint32_t& hi, uint32_t& lo)
{
    uint32_t hp;
    asm("cvt.rn.bf16x2.f32 %0, %1, %2;" : "=r"(hp) : "f"(x1), "f"(x0));
    float h0 = __uint_as_float(hp << 16);
    float h1 = __uint_as_float(hp & 0xffff0000u);
    float r0 = x0 - h0;
    float r1 = x1 - h1;
    uint32_t lp;
    asm("cvt.rn.bf16x2.f32 %0, %1, %2;" : "=r"(lp) : "f"(r1), "f"(r0));
    hi = hp;
    lo = lp;
}

__global__ void __launch_bounds__(256) gemm_mma_kernel(
    const float* __restrict__ x, const float* __restrict__ w, int M)
{
    __shared__ unsigned long long ws[64 * WS_STRIDE];

    const int tid  = threadIdx.x;
    const int wid  = tid >> 5;
    const int lane = tid & 31;
    const int q = lane >> 2;
    const int t = lane & 3;

    const int warp_m = blockIdx.x * 128 + wid * 16;
    const int row0 = warp_m + q;
    const int row1 = row0 + 8;
    const int row0c = row0 < M ? row0 : 0;
    const int row1c = row1 < M ? row1 : 0;
    const float* xr0 = x + (size_t)row0c * K_DIM;
    const float* xr1 = x + (size_t)row1c * K_DIM;

    float acc[8][4];
#pragma unroll
    for (int j = 0; j < 8; j++)
#pragma unroll
        for (int i = 0; i < 4; i++) acc[j][i] = 0.f;

    // prime the A pipeline (kstep 0)
    float2 ca = *(const float2*)(xr0 + 2 * t);
    float2 cc = *(const float2*)(xr1 + 2 * t);
    float2 cb = *(const float2*)(xr0 + 2 * t + 8);
    float2 cd = *(const float2*)(xr1 + 2 * t + 8);

#pragma unroll 1
    for (int stage = 0; stage < 2; stage++) {
        // ---- stage W K-half into smem (coalesced: n fastest)
#pragma unroll 1
        for (int idx = tid; idx < 4096; idx += 256) {
            int n = idx & 63;
            int p = idx >> 6;
            int k = stage * 128 + p * 2;
            float w0 = w[(size_t)k * N_DIM + n];
            float w1 = w[(size_t)(k + 1) * N_DIM + n];
            uint32_t hi, lo;
            split_pair(w0, w1, hi, lo);
            int kstep = p >> 3, pp = p & 7;
            ws[n * WS_STRIDE + kstep * 8 + (pp >> 2) * 4 + (pp & 3)] =
                ((unsigned long long)lo << 32) | (unsigned long long)hi;
        }
        __syncthreads();

#pragma unroll 1
        for (int ks = 0; ks < 8; ks++) {
            const int gks = stage * 8 + ks;
            // ---- prefetch next kstep's A (wraps to 0 on last; discarded)
            const int k0n = (gks < 15) ? (gks + 1) * 16 : 0;
            float2 na = *(const float2*)(xr0 + k0n + 2 * t);
            float2 nc = *(const float2*)(xr1 + k0n + 2 * t);
            float2 nb = *(const float2*)(xr0 + k0n + 2 * t + 8);
            float2 nd = *(const float2*)(xr1 + k0n + 2 * t + 8);

            // ---- convert current A
            uint32_t ah0, al0, ah1, al1, ah2, al2, ah3, al3;
            split_pair(ca.x, ca.y, ah0, al0);
            split_pair(cc.x, cc.y, ah1, al1);
            split_pair(cb.x, cb.y, ah2, al2);
            split_pair(cd.x, cd.y, ah3, al3);

#pragma unroll
            for (int j = 0; j < 8; j++) {
                const int n = j * 8 + q;
                unsigned long long w0 = ws[n * WS_STRIDE + ks * 8 + t];
                unsigned long long w1 = ws[n * WS_STRIDE + ks * 8 + 4 + t];
                uint32_t b0h = (uint32_t)w0, b0l = (uint32_t)(w0 >> 32);
                uint32_t b1h = (uint32_t)w1, b1l = (uint32_t)(w1 >> 32);
                mma_bf16(acc[j], ah0, ah1, ah2, ah3, b0h, b1h);   // hh
                mma_bf16(acc[j], ah0, ah1, ah2, ah3, b0l, b1l);   // hl
                mma_bf16(acc[j], al0, al1, al2, al3, b0h, b1h);   // lh
            }
            ca = na; cb = nb; cc = nc; cd = nd;
        }
        __syncthreads();
    }

#pragma unroll
    for (int j = 0; j < 8; j++) {
        int c = j * 8 + 2 * t;
        if (row0 < M)
            *(float2*)(g_pre + (size_t)row0 * N_DIM + c) =
                make_float2(acc[j][0], acc[j][1]);
        if (row1 < M)
            *(float2*)(g_pre + (size_t)row1 * N_DIM + c) =
                make_float2(acc[j][2], acc[j][3]);
    }
}

// ===========================================================================
// CSR build
// ===========================================================================
__global__ void zero_cnt_kernel(int N)
{
    int i = blockIdx.x * blockDim.x + threadIdx.x;
    if (i < N) g_row_cnt[i] = 0;
}

// 4 edges per thread for MLP; vector index loads on the int32 path
__global__ void hist_kernel(const void* __restrict__ rows_p, int E)
{
    int base = (blockIdx.x * blockDim.x + threadIdx.x) * 4;
    if (base >= E) return;
    if (!g_idx64 && base + 3 < E) {
        int4 r = *(const int4*)((const int*)rows_p + base);
        atomicAdd(&g_row_cnt[r.x], 1);
        atomicAdd(&g_row_cnt[r.y], 1);
        atomicAdd(&g_row_cnt[r.z], 1);
        atomicAdd(&g_row_cnt[r.w], 1);
    } else {
#pragma unroll
        for (int k = 0; k < 4; k++)
            if (base + k < E)
                atomicAdd(&g_row_cnt[load_idx(rows_p, base + k)], 1);
    }
}

// scan step 1: per-block sums of counts
__global__ void __launch_bounds__(SCAN_BLK) scan_partial_kernel(int N)
{
    __shared__ int warp_sums[32];
    int idx = blockIdx.x * SCAN_BLK + threadIdx.x;
    int v = (idx < N) ? g_row_cnt[idx] : 0;
#pragma unroll
    for (int o = 16; o > 0; o >>= 1) v += __shfl_down_sync(0xffffffffu, v, o);
    if ((threadIdx.x & 31) == 0) warp_sums[threadIdx.x >> 5] = v;
    __syncthreads();
    if (threadIdx.x < 32) {
        int s = warp_sums[threadIdx.x];
#pragma unroll
        for (int o = 16; o > 0; o >>= 1) s += __shfl_down_sync(0xffffffffu, s, o);
        if (threadIdx.x == 0) g_scan_part[blockIdx.x] = s;
    }
}

// scan step 2: serial exclusive scan of block partials (tiny)
__global__ void scan_base_kernel(int nblocks, int N)
{
    if (threadIdx.x == 0 && blockIdx.x == 0) {
        int run = 0;
        for (int b = 0; b < nblocks; b++) {
            int t = g_scan_part[b];
            g_scan_part[b] = run;
            run += t;
        }
        g_row_off[N] = run;   // = E
    }
}

// scan step 3: block-local exclusive scan + base -> offsets and cursor
__global__ void __launch_bounds__(SCAN_BLK) scan_write_kernel(int N)
{
    __shared__ int warp_sums[32];
    int idx = blockIdx.x * SCAN_BLK + threadIdx.x;
    int lane = threadIdx.x & 31;
    int wid = threadIdx.x >> 5;

    int v = (idx < N) ? g_row_cnt[idx] : 0;
    int incl = v;
#pragma unroll
    for (int o = 1; o < 32; o <<= 1) {
        int n = __shfl_up_sync(0xffffffffu, incl, o);
        if (lane >= o) incl += n;
    }
    if (lane == 31) warp_sums[wid] = incl;
    __syncthreads();
    if (wid == 0) {
        int s = (lane < 32) ? warp_sums[lane] : 0;
#pragma unroll
        for (int o = 1; o < 32; o <<= 1) {
            int n = __shfl_up_sync(0xffffffffu, s, o);
            if (lane >= o) s += n;
        }
        warp_sums[lane] = s;
    }
    __syncthreads();
    int warp_base = (wid == 0) ? 0 : warp_sums[wid - 1];
    int excl = g_scan_part[blockIdx.x] + warp_base + incl - v;
    if (idx < N) {
        g_row_off[idx] = excl;
        g_row_cnt[idx] = excl;   // becomes the permute cursor
    }
}

// permute: scatter (col,val) into row-sorted list; 4 edges per thread
__global__ void permute_kernel(const void* __restrict__ rows_p,
                               const void* __restrict__ cols_p,
                               const float* __restrict__ vals, int E)
{
    int base = (blockIdx.x * blockDim.x + threadIdx.x) * 4;
    if (base >= E) return;
    if (!g_idx64 && base + 3 < E) {
        int4 r = *(const int4*)((const int*)rows_p + base);
        int4 c = *(const int4*)((const int*)cols_p + base);
        float4 v = *(const float4*)(vals + base);
        int p0 = atomicAdd(&g_row_cnt[r.x], 1);
        int p1 = atomicAdd(&g_row_cnt[r.y], 1);
        int p2 = atomicAdd(&g_row_cnt[r.z], 1);
        int p3 = atomicAdd(&g_row_cnt[r.w], 1);
        g_edge_cv[p0] = ((unsigned long long)__float_as_uint(v.x) << 32) | (unsigned int)c.x;
        g_edge_cv[p1] = ((unsigned long long)__float_as_uint(v.y) << 32) | (unsigned int)c.y;
        g_edge_cv[p2] = ((unsigned long long)__float_as_uint(v.z) << 32) | (unsigned int)c.z;
        g_edge_cv[p3] = ((unsigned long long)__float_as_uint(v.w) << 32) | (unsigned int)c.w;
    } else {
#pragma unroll
        for (int k = 0; k < 4; k++) {
            int e = base + k;
            if (e < E) {
                int r = load_idx(rows_p, e);
                int c = load_idx(cols_p, e);
                int pos = atomicAdd(&g_row_cnt[r], 1);
                g_edge_cv[pos] =
                    ((unsigned long long)__float_as_uint(vals[e]) << 32) | (unsigned int)c;
            }
        }
    }
}

// ===========================================================================
// Gather-reduce: out[r,:] = relu( sum_e val*pre_sup[col,:] + bias )
// 16 threads per row (thread owns one float4 quad); warp covers 2 rows.
// ===========================================================================
__global__ void __launch_bounds__(256) gather_kernel(
    const float* __restrict__ bias, float* __restrict__ out, int N)
{
    int r = blockIdx.x * 16 + (threadIdx.x >> 4);
    int q = threadIdx.x & 15;
    if (r >= N) return;

    int i   = g_row_off[r];
    int end = g_row_off[r + 1];

    float4 acc = make_float4(0.f, 0.f, 0.f, 0.f);
    for (; i < end; i++) {
        unsigned long long cv = g_edge_cv[i];
        int c   = (int)(unsigned int)cv;
        float v = __uint_as_float((unsigned int)(cv >> 32));
        float4 p = *(const float4*)(g_pre + (size_t)c * N_DIM + q * 4);
        acc.x = fmaf(v, p.x, acc.x);
        acc.y = fmaf(v, p.y, acc.y);
        acc.z = fmaf(v, p.z, acc.z);
        acc.w = fmaf(v, p.w, acc.w);
    }

    float4 b = *(const float4*)(bias + q * 4);
    float4 o;
    o.x = fmaxf(acc.x + b.x, 0.f);
    o.y = fmaxf(acc.y + b.y, 0.f);
    o.z = fmaxf(acc.z + b.z, 0.f);
    o.w = fmaxf(acc.w + b.w, 0.f);
    *(float4*)(out + (size_t)r * N_DIM + q * 4) = o;
}

// ===========================================================================
// Launch
// Inputs: 0:x f32[N,256]  1:rows i32/i64[E]  2:cols i32/i64[E]
//         3:vals f32[E]   4:weight f32[256,64]  5:bias f32[64]
// Output: f32 [N, 64]
// ===========================================================================
extern "C" void kernel_launch(void* const* d_in, const int* in_sizes, int n_in,
                              void* d_out, int out_size)
{
    const float* x    = (const float*)d_in[0];
    const void*  rows = d_in[1];
    const void*  cols = d_in[2];
    const float* vals = (const float*)d_in[3];
    const float* w    = (const float*)d_in[4];
    const float* bias = (const float*)d_in[5];
    float*       out  = (float*)d_out;

    const int N = in_sizes[0] / K_DIM;
    const int E = in_sizes[1];
    const int scan_blocks = (N + SCAN_BLK - 1) / SCAN_BLK;
    const int e4_blocks = ((E + 3) / 4 + 255) / 256;

    detect_idx_kernel<<<1, 1024>>>((const unsigned int*)rows, E);
    gemm_mma_kernel<<<(N + 127) / 128, 256>>>(x, w, N);
    zero_cnt_kernel<<<(N + 1023) / 1024, 1024>>>(N);
    hist_kernel<<<e4_blocks, 256>>>(rows, E);
    scan_partial_kernel<<<scan_blocks, SCAN_BLK>>>(N);
    scan_base_kernel<<<1, 32>>>(scan_blocks, N);
    scan_write_kernel<<<scan_blocks, SCAN_BLK>>>(N);
    permute_kernel<<<e4_blocks, 256>>>(rows, cols, vals, E);
    gather_kernel<<<(N + 15) / 16, 256>>>(bias, out, N);
}